// round 2
// baseline (speedup 1.0000x reference)
#include <cuda_runtime.h>

#define N_GAUSS 4096
#define N_PTS 32768
#define NSPLIT 8
#define GPS (N_GAUSS / NSPLIT)   /* 512 gaussians per split */
#define TILE 128
#define F4G 7                    /* float4 per gaussian (28 floats) */

__device__ float4 g_prm[N_GAUSS * F4G];
__device__ float g_partial[NSPLIT * 2 * N_PTS];

__device__ __forceinline__ float ex2f(float x) {
    float y; asm("ex2.approx.ftz.f32 %0, %1;" : "=f"(y) : "f"(x)); return y;
}
__device__ __forceinline__ float rsqf(float x) {
    float y; asm("rsqrt.approx.ftz.f32 %0, %1;" : "=f"(y) : "f"(x)); return y;
}

// ---------------------------------------------------------------------------
// Per-gaussian preprocessing: precision matrix (with -0.5*log2e folded in,
// off-diagonals doubled), sigmoid opacity, SH coefficients with the basis
// constants folded in. 28 floats per gaussian, float4-aligned.
// ---------------------------------------------------------------------------
__global__ void prep_kernel(const float* __restrict__ xyz,
                            const float* __restrict__ sh_dc,
                            const float* __restrict__ sh_rest,
                            const float* __restrict__ scaling,
                            const float* __restrict__ rotation,
                            const float* __restrict__ opacity) {
    int g = blockIdx.x * blockDim.x + threadIdx.x;
    if (g >= N_GAUSS) return;

    float qr = rotation[g*4+0], qx = rotation[g*4+1];
    float qy = rotation[g*4+2], qz = rotation[g*4+3];
    float qn = rsqrtf(qr*qr + qx*qx + qy*qy + qz*qz);
    qr *= qn; qx *= qn; qy *= qn; qz *= qn;

    float R00 = 1.f - 2.f*(qy*qy + qz*qz), R01 = 2.f*(qx*qy - qr*qz), R02 = 2.f*(qx*qz + qr*qy);
    float R10 = 2.f*(qx*qy + qr*qz), R11 = 1.f - 2.f*(qx*qx + qz*qz), R12 = 2.f*(qy*qz - qr*qx);
    float R20 = 2.f*(qx*qz - qr*qy), R21 = 2.f*(qy*qz + qr*qx), R22 = 1.f - 2.f*(qx*qx + qy*qy);

    float iv0 = expf(-2.f * scaling[g*3+0]);
    float iv1 = expf(-2.f * scaling[g*3+1]);
    float iv2 = expf(-2.f * scaling[g*3+2]);

    // prec[a][b] = sum_j iv[j] * R[a][j] * R[b][j]
    float Pxx = iv0*R00*R00 + iv1*R01*R01 + iv2*R02*R02;
    float Pyy = iv0*R10*R10 + iv1*R11*R11 + iv2*R12*R12;
    float Pzz = iv0*R20*R20 + iv1*R21*R21 + iv2*R22*R22;
    float Pxy = iv0*R00*R10 + iv1*R01*R11 + iv2*R02*R12;
    float Pxz = iv0*R00*R20 + iv1*R01*R21 + iv2*R02*R22;
    float Pyz = iv0*R10*R20 + iv1*R11*R21 + iv2*R12*R22;

    const float kk = -0.7213475204444817f;  // -0.5 * log2(e)
    float op = 1.f / (1.f + expf(-opacity[g]));

    const float C0 = 0.28209479177387814f;
    const float C1 = 0.4886025119029199f;
    const float* sr = sh_rest + g*15;
    float c0  =  C0 * sh_dc[g];
    float c1  = -C1 * sr[0];
    float c2  =  C1 * sr[1];
    float c3  = -C1 * sr[2];
    float c4  =  1.0925484305920792f  * sr[3];
    float c5  = -1.0925484305920792f  * sr[4];
    float c6  =  0.31539156525252005f * sr[5];
    float c7  = -1.0925484305920792f  * sr[6];
    float c8  =  0.5462742152960396f  * sr[7];
    float c9  = -0.5900435899266435f  * sr[8];
    float c10 =  2.890611442640554f   * sr[9];
    float c11 = -0.4570457994644658f  * sr[10];
    float c12 =  0.3731763325901154f  * sr[11];
    float c13 = -0.4570457994644658f  * sr[12];
    float c14 =  1.445305721320277f   * sr[13];
    float c15 = -0.5900435899266435f  * sr[14];

    float4* o = &g_prm[g * F4G];
    o[0] = make_float4(xyz[g*3+0], xyz[g*3+1], xyz[g*3+2], op);
    o[1] = make_float4(kk*Pxx, kk*Pyy, kk*Pzz, 2.f*kk*Pxy);
    o[2] = make_float4(2.f*kk*Pxz, 2.f*kk*Pyz, c0, c1);
    o[3] = make_float4(c2, c3, c4, c5);
    o[4] = make_float4(c6, c7, c8, c9);
    o[5] = make_float4(c10, c11, c12, c13);
    o[6] = make_float4(c14, c15, 0.f, 0.f);
}

// ---------------------------------------------------------------------------
// Main kernel: one thread per point, gaussian dimension split across
// blockIdx.y (NSPLIT partials, reduced later — deterministic, no atomics).
// Gaussian params streamed through SMEM in 128-gaussian tiles as float4.
// ---------------------------------------------------------------------------
__global__ void __launch_bounds__(256) main_kernel(const float* __restrict__ pts) {
    int pt = blockIdx.x * 256 + threadIdx.x;
    int split = blockIdx.y;

    float px = pts[pt*3+0];
    float py = pts[pt*3+1];
    float pz = pts[pt*3+2];

    __shared__ float4 s4[TILE * F4G];

    float wsum = 0.f, ssum = 0.f;
    int gbase = split * GPS;

    for (int t = 0; t < GPS; t += TILE) {
        __syncthreads();
        const float4* src = &g_prm[(gbase + t) * F4G];
        for (int i = threadIdx.x; i < TILE * F4G; i += 256) s4[i] = src[i];
        __syncthreads();

#pragma unroll 4
        for (int j = 0; j < TILE; ++j) {
            const float4* G = &s4[j * F4G];
            float4 v0 = G[0];
            float dx = px - v0.x, dy = py - v0.y, dz = pz - v0.z;
            float4 v1 = G[1];
            float dxx = dx*dx, dyy = dy*dy, dzz = dz*dz;
            float n2 = dxx + dyy + dzz;
            // exponent (already scaled by -0.5*log2e)
            float m = dxx*v1.x;
            m = fmaf(dyy, v1.y, m);
            m = fmaf(dzz, v1.z, m);
            m = fmaf(dx*dy, v1.w, m);
            float4 v2 = G[2];
            m = fmaf(dx*dz, v2.x, m);
            m = fmaf(dy*dz, v2.y, m);

            float rinv = rsqf(n2);
            float x = -dx*rinv, y = -dy*rinv, z = -dz*rinv;
            float xx = x*x, yy = y*y, zz = z*z;
            float xy = x*y, yz = y*z, xz = x*z;

            // SH degree 3 (coefficients pre-folded; unit-dir identities used)
            float res = fmaf(y, v2.w, v2.z);             // c0 + c1*y
            float4 v3 = G[3];
            res = fmaf(z, v3.x, res);                    // c2*z
            res = fmaf(x, v3.y, res);                    // c3*x
            res = fmaf(xy, v3.z, res);                   // c4*xy
            res = fmaf(yz, v3.w, res);                   // c5*yz
            float4 v4 = G[4];
            res = fmaf(fmaf(3.f, zz, -1.f), v4.x, res);  // c6*(2zz-xx-yy)
            res = fmaf(xz, v4.y, res);                   // c7*xz
            float u = xx - yy;
            res = fmaf(u, v4.z, res);                    // c8*(xx-yy)
            res = fmaf(y*fmaf(3.f, xx, -yy), v4.w, res); // c9*y(3xx-yy)
            float4 v5 = G[5];
            res = fmaf(xy*z, v5.x, res);                 // c10*xyz
            float w5 = fmaf(5.f, zz, -1.f);
            res = fmaf(y*w5, v5.y, res);                 // c11*y(4zz-xx-yy)
            res = fmaf(z*fmaf(5.f, zz, -3.f), v5.z, res);// c12*z(2zz-3xx-3yy)
            res = fmaf(x*w5, v5.w, res);                 // c13*x(4zz-xx-yy)
            float4 v6 = G[6];
            res = fmaf(z*u, v6.x, res);                  // c14*z(xx-yy)
            res = fmaf(x*fmaf(-3.f, zz, u), v6.y, res);  // c15*x(xx-yy-3zz)

            float mag = fmaxf(res, 0.f);
            float w = v0.w * ex2f(m);
            wsum += w;
            ssum = fmaf(w, mag, ssum);
        }
    }

    g_partial[(split*2 + 0)*N_PTS + pt] = wsum;
    g_partial[(split*2 + 1)*N_PTS + pt] = ssum;
}

// ---------------------------------------------------------------------------
// Deterministic fixed-order reduction of the NSPLIT partials.
// out[0:N_PTS] = opacity sums, out[N_PTS:2*N_PTS] = signal sums.
// ---------------------------------------------------------------------------
__global__ void reduce_kernel(float* __restrict__ out) {
    int i = blockIdx.x * blockDim.x + threadIdx.x;
    if (i >= 2 * N_PTS) return;
    int which = (i >= N_PTS) ? 1 : 0;
    int pt = i - which * N_PTS;
    float a = 0.f;
#pragma unroll
    for (int s = 0; s < NSPLIT; ++s) a += g_partial[(s*2 + which)*N_PTS + pt];
    out[i] = a;
}

extern "C" void kernel_launch(void* const* d_in, const int* in_sizes, int n_in,
                              void* d_out, int out_size) {
    const float* pts      = (const float*)d_in[0];  // network_pts
    // d_in[1] network_view, d_in[2] network_tx: unused by the reference math
    const float* xyz      = (const float*)d_in[3];
    const float* sh_dc    = (const float*)d_in[4];
    const float* sh_rest  = (const float*)d_in[5];
    const float* scaling  = (const float*)d_in[6];
    const float* rotation = (const float*)d_in[7];
    const float* opacity  = (const float*)d_in[8];

    prep_kernel<<<(N_GAUSS + 255)/256, 256>>>(xyz, sh_dc, sh_rest, scaling, rotation, opacity);
    main_kernel<<<dim3(N_PTS/256, NSPLIT), 256>>>(pts);
    reduce_kernel<<<(2*N_PTS + 255)/256, 256>>>((float*)d_out);
}

// round 3
// speedup vs baseline: 1.0618x; 1.0618x over previous
#include <cuda_runtime.h>

#define N_GAUSS 4096
#define N_PTS 32768
#define HALF_PTS (N_PTS/2)
#define NSPLIT 8
#define GPS (N_GAUSS / NSPLIT)   /* 512 gaussians per split */
#define TILE 128
#define U2G 13                   /* ulonglong2 per gaussian (26 dup-params) */

typedef unsigned long long u64;

__device__ ulonglong2 g_prm2[N_GAUSS * U2G];
__device__ float g_partial[NSPLIT * 2 * N_PTS];

__device__ __forceinline__ float ex2f(float x) {
    float y; asm("ex2.approx.ftz.f32 %0, %1;" : "=f"(y) : "f"(x)); return y;
}
__device__ __forceinline__ float rsqf(float x) {
    float y; asm("rsqrt.approx.ftz.f32 %0, %1;" : "=f"(y) : "f"(x)); return y;
}
__device__ __forceinline__ u64 f2fma(u64 a, u64 b, u64 c) {
    u64 d; asm("fma.rn.f32x2 %0, %1, %2, %3;" : "=l"(d) : "l"(a), "l"(b), "l"(c)); return d;
}
__device__ __forceinline__ u64 f2mul(u64 a, u64 b) {
    u64 d; asm("mul.rn.f32x2 %0, %1, %2;" : "=l"(d) : "l"(a), "l"(b)); return d;
}
__device__ __forceinline__ u64 f2add(u64 a, u64 b) {
    u64 d; asm("add.rn.f32x2 %0, %1, %2;" : "=l"(d) : "l"(a), "l"(b)); return d;
}
__device__ __forceinline__ u64 f2pack(float lo, float hi) {
    u64 d; asm("mov.b64 %0, {%1, %2};" : "=l"(d) : "f"(lo), "f"(hi)); return d;
}
__device__ __forceinline__ void f2unpack(u64 v, float& lo, float& hi) {
    asm("mov.b64 {%0, %1}, %2;" : "=f"(lo), "=f"(hi) : "l"(v));
}

// ---------------------------------------------------------------------------
// Per-gaussian preprocessing. Each param stored DUPLICATED {v,v} so the main
// kernel's packed f32x2 ops can consume SMEM operands directly (no splats).
// Layout per gaussian (13 ulonglong2 = 26 float2 slots):
//  q0={gx,gy} q1={gz,P0} q2={P1,P2} q3={P3,P4} q4={P5,op}
//  q5={c0,c1} q6={c2,c3} q7={c4,c5} q8={c6,c7} q9={c8,c9}
//  q10={c10,c11} q11={c12,c13} q12={c14,c15}
// P* = precision entries pre-scaled by -0.5*log2(e), off-diagonals doubled.
// ---------------------------------------------------------------------------
__global__ void prep_kernel(const float* __restrict__ xyz,
                            const float* __restrict__ sh_dc,
                            const float* __restrict__ sh_rest,
                            const float* __restrict__ scaling,
                            const float* __restrict__ rotation,
                            const float* __restrict__ opacity) {
    int g = blockIdx.x * blockDim.x + threadIdx.x;
    if (g >= N_GAUSS) return;

    float qr = rotation[g*4+0], qx = rotation[g*4+1];
    float qy = rotation[g*4+2], qz = rotation[g*4+3];
    float qn = rsqrtf(qr*qr + qx*qx + qy*qy + qz*qz);
    qr *= qn; qx *= qn; qy *= qn; qz *= qn;

    float R00 = 1.f - 2.f*(qy*qy + qz*qz), R01 = 2.f*(qx*qy - qr*qz), R02 = 2.f*(qx*qz + qr*qy);
    float R10 = 2.f*(qx*qy + qr*qz), R11 = 1.f - 2.f*(qx*qx + qz*qz), R12 = 2.f*(qy*qz - qr*qx);
    float R20 = 2.f*(qx*qz - qr*qy), R21 = 2.f*(qy*qz + qr*qx), R22 = 1.f - 2.f*(qx*qx + qy*qy);

    float iv0 = expf(-2.f * scaling[g*3+0]);
    float iv1 = expf(-2.f * scaling[g*3+1]);
    float iv2 = expf(-2.f * scaling[g*3+2]);

    float Pxx = iv0*R00*R00 + iv1*R01*R01 + iv2*R02*R02;
    float Pyy = iv0*R10*R10 + iv1*R11*R11 + iv2*R12*R12;
    float Pzz = iv0*R20*R20 + iv1*R21*R21 + iv2*R22*R22;
    float Pxy = iv0*R00*R10 + iv1*R01*R11 + iv2*R02*R12;
    float Pxz = iv0*R00*R20 + iv1*R01*R21 + iv2*R02*R22;
    float Pyz = iv0*R10*R20 + iv1*R11*R21 + iv2*R12*R22;

    const float kk = -0.7213475204444817f;  // -0.5 * log2(e)
    float op = 1.f / (1.f + expf(-opacity[g]));

    const float C0 = 0.28209479177387814f;
    const float C1 = 0.4886025119029199f;
    const float* sr = sh_rest + g*15;
    float c[16];
    c[0]  =  C0 * sh_dc[g];
    c[1]  = -C1 * sr[0];
    c[2]  =  C1 * sr[1];
    c[3]  = -C1 * sr[2];
    c[4]  =  1.0925484305920792f  * sr[3];
    c[5]  = -1.0925484305920792f  * sr[4];
    c[6]  =  0.31539156525252005f * sr[5];
    c[7]  = -1.0925484305920792f  * sr[6];
    c[8]  =  0.5462742152960396f  * sr[7];
    c[9]  = -0.5900435899266435f  * sr[8];
    c[10] =  2.890611442640554f   * sr[9];
    c[11] = -0.4570457994644658f  * sr[10];
    c[12] =  0.3731763325901154f  * sr[11];
    c[13] = -0.4570457994644658f  * sr[12];
    c[14] =  1.445305721320277f   * sr[13];
    c[15] = -0.5900435899266435f  * sr[14];

    float2* o = (float2*)&g_prm2[g * U2G];  // 26 float2 slots
    float v[26];
    v[0] = xyz[g*3+0]; v[1] = xyz[g*3+1]; v[2] = xyz[g*3+2];
    v[3] = kk*Pxx; v[4] = kk*Pyy; v[5] = kk*Pzz;
    v[6] = 2.f*kk*Pxy; v[7] = 2.f*kk*Pxz; v[8] = 2.f*kk*Pyz;
    v[9] = op;
#pragma unroll
    for (int i = 0; i < 16; ++i) v[10+i] = c[i];
#pragma unroll
    for (int i = 0; i < 26; ++i) o[i] = make_float2(v[i], v[i]);
}

// ---------------------------------------------------------------------------
// Main kernel: 2 points per thread via packed f32x2 math. Gaussian dimension
// split over blockIdx.y (deterministic partials, fixed-order reduce after).
// ---------------------------------------------------------------------------
__global__ void __launch_bounds__(128) main_kernel(const float* __restrict__ pts) {
    int tid = threadIdx.x;
    int ptA = blockIdx.x * 128 + tid;
    int ptB = ptA + HALF_PTS;
    int split = blockIdx.y;

    // negated points packed {A,B}
    u64 npx = f2pack(-pts[ptA*3+0], -pts[ptB*3+0]);
    u64 npy = f2pack(-pts[ptA*3+1], -pts[ptB*3+1]);
    u64 npz = f2pack(-pts[ptA*3+2], -pts[ptB*3+2]);

    const u64 K3  = 0x4040000040400000ULL;  // { 3, 3}
    const u64 Kn1 = 0xBF800000BF800000ULL;  // {-1,-1}
    const u64 K5  = 0x40A0000040A00000ULL;  // { 5, 5}
    const u64 Kn3 = 0xC0400000C0400000ULL;  // {-3,-3}

    __shared__ ulonglong2 sB[TILE * U2G];

    float wsumA = 0.f, wsumB = 0.f, ssumA = 0.f, ssumB = 0.f;
    int gbase = split * GPS;

    for (int t = 0; t < GPS; t += TILE) {
        __syncthreads();
        const ulonglong2* src = &g_prm2[(gbase + t) * U2G];
        for (int i = tid; i < TILE * U2G; i += 128) sB[i] = src[i];
        __syncthreads();

#pragma unroll 2
        for (int j = 0; j < TILE; ++j) {
            const ulonglong2* G = &sB[j * U2G];
            ulonglong2 q0 = G[0], q1 = G[1], q2 = G[2], q3 = G[3], q4 = G[4];

            u64 ex = f2add(q0.x, npx);           // gauss - point (sign-flipped diff)
            u64 ey = f2add(q0.y, npy);
            u64 ez = f2add(q1.x, npz);
            u64 exx = f2mul(ex, ex), eyy = f2mul(ey, ey), ezz = f2mul(ez, ez);
            u64 n2 = f2add(exx, f2add(eyy, ezz));

            // exponent (quadratic form is sign-invariant; -0.5*log2e pre-folded)
            u64 mm = f2mul(exx, q1.y);
            mm = f2fma(eyy, q2.x, mm);
            mm = f2fma(ezz, q2.y, mm);
            mm = f2fma(f2mul(ex, ey), q3.x, mm);
            mm = f2fma(f2mul(ex, ez), q3.y, mm);
            mm = f2fma(f2mul(ey, ez), q4.x, mm);

            float nA, nB; f2unpack(n2, nA, nB);
            u64 rinv = f2pack(rsqf(nA), rsqf(nB));
            u64 x = f2mul(ex, rinv), y = f2mul(ey, rinv), z = f2mul(ez, rinv);
            u64 xx = f2mul(x, x), yy = f2mul(y, y), zz = f2mul(z, z);
            u64 xy = f2mul(x, y), yz = f2mul(y, z), xz = f2mul(x, z);

            ulonglong2 q5 = G[5], q6 = G[6], q7 = G[7], q8 = G[8], q9 = G[9];
            u64 res = f2fma(y, q5.y, q5.x);                    // c0 + c1*y
            res = f2fma(z, q6.x, res);                         // c2*z
            res = f2fma(x, q6.y, res);                         // c3*x
            res = f2fma(xy, q7.x, res);                        // c4*xy
            res = f2fma(yz, q7.y, res);                        // c5*yz
            u64 t6 = f2fma(K3, zz, Kn1);                       // 3zz-1 = 2zz-xx-yy
            res = f2fma(t6, q8.x, res);                        // c6
            res = f2fma(xz, q8.y, res);                        // c7*xz
            u64 nyy = f2mul(yy, Kn1);
            u64 u = f2add(xx, nyy);                            // xx-yy
            res = f2fma(u, q9.x, res);                         // c8
            u64 t9 = f2fma(K3, xx, nyy);                       // 3xx-yy
            res = f2fma(f2mul(y, t9), q9.y, res);              // c9
            ulonglong2 q10 = G[10], q11 = G[11], q12 = G[12];
            res = f2fma(f2mul(xy, z), q10.x, res);             // c10*xyz
            u64 w5 = f2fma(K5, zz, Kn1);                       // 5zz-1 = 4zz-xx-yy
            res = f2fma(f2mul(y, w5), q10.y, res);             // c11
            u64 t12 = f2fma(K5, zz, Kn3);                      // 5zz-3 = 2zz-3xx-3yy
            res = f2fma(f2mul(z, t12), q11.x, res);            // c12
            res = f2fma(f2mul(x, w5), q11.y, res);             // c13
            res = f2fma(f2mul(z, u), q12.x, res);              // c14
            u64 t15 = f2fma(Kn3, zz, u);                       // xx-yy-3zz
            res = f2fma(f2mul(x, t15), q12.y, res);            // c15

            float mA, mB; f2unpack(mm, mA, mB);
            float rA, rB; f2unpack(res, rA, rB);
            float opv, opv2; f2unpack(q4.y, opv, opv2);
            float wA = opv * ex2f(mA);
            float wB = opv * ex2f(mB);
            wsumA += wA; wsumB += wB;
            ssumA = fmaf(wA, fmaxf(rA, 0.f), ssumA);
            ssumB = fmaf(wB, fmaxf(rB, 0.f), ssumB);
        }
    }

    g_partial[(split*2 + 0)*N_PTS + ptA] = wsumA;
    g_partial[(split*2 + 0)*N_PTS + ptB] = wsumB;
    g_partial[(split*2 + 1)*N_PTS + ptA] = ssumA;
    g_partial[(split*2 + 1)*N_PTS + ptB] = ssumB;
}

// ---------------------------------------------------------------------------
// Deterministic fixed-order reduction of the NSPLIT partials.
// ---------------------------------------------------------------------------
__global__ void reduce_kernel(float* __restrict__ out) {
    int i = blockIdx.x * blockDim.x + threadIdx.x;
    if (i >= 2 * N_PTS) return;
    int which = (i >= N_PTS) ? 1 : 0;
    int pt = i - which * N_PTS;
    float a = 0.f;
#pragma unroll
    for (int s = 0; s < NSPLIT; ++s) a += g_partial[(s*2 + which)*N_PTS + pt];
    out[i] = a;
}

extern "C" void kernel_launch(void* const* d_in, const int* in_sizes, int n_in,
                              void* d_out, int out_size) {
    const float* pts      = (const float*)d_in[0];  // network_pts
    // d_in[1] network_view, d_in[2] network_tx: unused by the reference math
    const float* xyz      = (const float*)d_in[3];
    const float* sh_dc    = (const float*)d_in[4];
    const float* sh_rest  = (const float*)d_in[5];
    const float* scaling  = (const float*)d_in[6];
    const float* rotation = (const float*)d_in[7];
    const float* opacity  = (const float*)d_in[8];

    prep_kernel<<<(N_GAUSS + 255)/256, 256>>>(xyz, sh_dc, sh_rest, scaling, rotation, opacity);
    main_kernel<<<dim3(HALF_PTS/128, NSPLIT), 128>>>(pts);
    reduce_kernel<<<(2*N_PTS + 255)/256, 256>>>((float*)d_out);
}

// round 4
// speedup vs baseline: 2.4059x; 2.2658x over previous
#include <cuda_runtime.h>

#define N_GAUSS 4096
#define N_PTS 32768
#define NSPLIT 8
#define GPS (N_GAUSS / NSPLIT)   /* 512 gaussians per split */
#define TILE 128
#define U2G 14                   /* ulonglong2 per gaussian (28 dup float2 slots) */
#define NCELL 4096               /* 16^3 grid */

typedef unsigned long long u64;

__device__ ulonglong2 g_prm2[N_GAUSS * U2G];
__device__ float g_partial[NSPLIT * 2 * N_PTS];
__device__ int    g_cnt[NCELL];
__device__ int    g_cur[NCELL];
__device__ int    g_cid[N_PTS];
__device__ int    g_perm[N_PTS];
__device__ float4 g_spts[N_PTS];

__device__ __forceinline__ float ex2f(float x) {
    float y; asm("ex2.approx.ftz.f32 %0, %1;" : "=f"(y) : "f"(x)); return y;
}
__device__ __forceinline__ float rsqf(float x) {
    float y; asm("rsqrt.approx.ftz.f32 %0, %1;" : "=f"(y) : "f"(x)); return y;
}
__device__ __forceinline__ u64 f2fma(u64 a, u64 b, u64 c) {
    u64 d; asm("fma.rn.f32x2 %0, %1, %2, %3;" : "=l"(d) : "l"(a), "l"(b), "l"(c)); return d;
}
__device__ __forceinline__ u64 f2mul(u64 a, u64 b) {
    u64 d; asm("mul.rn.f32x2 %0, %1, %2;" : "=l"(d) : "l"(a), "l"(b)); return d;
}
__device__ __forceinline__ u64 f2add(u64 a, u64 b) {
    u64 d; asm("add.rn.f32x2 %0, %1, %2;" : "=l"(d) : "l"(a), "l"(b)); return d;
}
__device__ __forceinline__ u64 f2pack(float lo, float hi) {
    u64 d; asm("mov.b64 %0, {%1, %2};" : "=l"(d) : "f"(lo), "f"(hi)); return d;
}
__device__ __forceinline__ void f2unpack(u64 v, float& lo, float& hi) {
    asm("mov.b64 {%0, %1}, %2;" : "=f"(lo), "=f"(hi) : "l"(v));
}
// branch-free packed ReLU via sign masking (alu pipe; avoids max.f32x2 risk)
__device__ __forceinline__ u64 f2relu(u64 v) {
    unsigned lo = (unsigned)v, hi = (unsigned)(v >> 32);
    lo &= ~(unsigned)(((int)lo) >> 31);
    hi &= ~(unsigned)(((int)hi) >> 31);
    return ((u64)hi << 32) | lo;
}

// ---------------------------------------------------------------------------
// Spatial binning of points (cell = 0.5, 16^3 over [-4,4]).
// Point order nondeterminism within a cell is harmless: each point's gaussian
// sum is computed identically regardless of which lane/slot processes it, and
// results are written back through the permutation.
// ---------------------------------------------------------------------------
__global__ void zero_kernel() {
    int i = blockIdx.x * blockDim.x + threadIdx.x;
    if (i < NCELL) g_cnt[i] = 0;
}

__global__ void cell_count(const float* __restrict__ pts) {
    int i = blockIdx.x * blockDim.x + threadIdx.x;
    if (i >= N_PTS) return;
    float x = pts[i*3+0], y = pts[i*3+1], z = pts[i*3+2];
    int ix = min(15, max(0, (int)floorf((x + 4.f) * 2.f)));
    int iy = min(15, max(0, (int)floorf((y + 4.f) * 2.f)));
    int iz = min(15, max(0, (int)floorf((z + 4.f) * 2.f)));
    int c = ix | (iy << 4) | (iz << 8);
    g_cid[i] = c;
    atomicAdd(&g_cnt[c], 1);
}

__global__ void __launch_bounds__(1024) scan_kernel() {
    __shared__ int ps[1024];
    int t = threadIdx.x;
    int l0 = g_cnt[t*4+0], l1 = g_cnt[t*4+1], l2 = g_cnt[t*4+2], l3 = g_cnt[t*4+3];
    int s = l0 + l1 + l2 + l3;
    ps[t] = s; __syncthreads();
    for (int off = 1; off < 1024; off <<= 1) {
        int v = (t >= off) ? ps[t - off] : 0;
        __syncthreads();
        ps[t] += v;
        __syncthreads();
    }
    int run = ps[t] - s;  // exclusive prefix for this thread's 4 cells
    g_cur[t*4+0] = run; run += l0;
    g_cur[t*4+1] = run; run += l1;
    g_cur[t*4+2] = run; run += l2;
    g_cur[t*4+3] = run;
}

__global__ void scatter_kernel(const float* __restrict__ pts) {
    int i = blockIdx.x * blockDim.x + threadIdx.x;
    if (i >= N_PTS) return;
    int slot = atomicAdd(&g_cur[g_cid[i]], 1);
    g_perm[slot] = i;
    // store NEGATED coords (main kernel computes e = g + (-p))
    g_spts[slot] = make_float4(-pts[i*3+0], -pts[i*3+1], -pts[i*3+2], 0.f);
}

// ---------------------------------------------------------------------------
// Per-gaussian preprocessing. 28 duplicated float2 slots per gaussian:
//  0:gx 1:gy 2:gz 3:T 4..9:P0..P5 10:op 11:c0 12..27:c1..c15
// P* pre-scaled by -0.5*log2(e), off-diagonals doubled.
// T = 230 * s_max^2 : pairs with |e|^2 >= T have exp(-0.5*maha) == 0.0f
// exactly (fp32, incl. denormals) in the reference as well -> lossless cull.
// ---------------------------------------------------------------------------
__global__ void prep_kernel(const float* __restrict__ xyz,
                            const float* __restrict__ sh_dc,
                            const float* __restrict__ sh_rest,
                            const float* __restrict__ scaling,
                            const float* __restrict__ rotation,
                            const float* __restrict__ opacity) {
    int g = blockIdx.x * blockDim.x + threadIdx.x;
    if (g >= N_GAUSS) return;

    float qr = rotation[g*4+0], qx = rotation[g*4+1];
    float qy = rotation[g*4+2], qz = rotation[g*4+3];
    float qn = rsqrtf(qr*qr + qx*qx + qy*qy + qz*qz);
    qr *= qn; qx *= qn; qy *= qn; qz *= qn;

    float R00 = 1.f - 2.f*(qy*qy + qz*qz), R01 = 2.f*(qx*qy - qr*qz), R02 = 2.f*(qx*qz + qr*qy);
    float R10 = 2.f*(qx*qy + qr*qz), R11 = 1.f - 2.f*(qx*qx + qz*qz), R12 = 2.f*(qy*qz - qr*qx);
    float R20 = 2.f*(qx*qz - qr*qy), R21 = 2.f*(qy*qz + qr*qx), R22 = 1.f - 2.f*(qx*qx + qy*qy);

    float s0 = expf(scaling[g*3+0]);
    float s1 = expf(scaling[g*3+1]);
    float s2 = expf(scaling[g*3+2]);
    float iv0 = 1.f/(s0*s0), iv1 = 1.f/(s1*s1), iv2 = 1.f/(s2*s2);
    float smax = fmaxf(s0, fmaxf(s1, s2));
    float T = 230.f * smax * smax;

    float Pxx = iv0*R00*R00 + iv1*R01*R01 + iv2*R02*R02;
    float Pyy = iv0*R10*R10 + iv1*R11*R11 + iv2*R12*R12;
    float Pzz = iv0*R20*R20 + iv1*R21*R21 + iv2*R22*R22;
    float Pxy = iv0*R00*R10 + iv1*R01*R11 + iv2*R02*R12;
    float Pxz = iv0*R00*R20 + iv1*R01*R21 + iv2*R02*R22;
    float Pyz = iv0*R10*R20 + iv1*R11*R21 + iv2*R12*R22;

    const float kk = -0.7213475204444817f;  // -0.5 * log2(e)
    float op = 1.f / (1.f + expf(-opacity[g]));

    const float C0 = 0.28209479177387814f;
    const float C1 = 0.4886025119029199f;
    const float* sr = sh_rest + g*15;
    float c[16];
    c[0]  =  C0 * sh_dc[g];
    c[1]  = -C1 * sr[0];
    c[2]  =  C1 * sr[1];
    c[3]  = -C1 * sr[2];
    c[4]  =  1.0925484305920792f  * sr[3];
    c[5]  = -1.0925484305920792f  * sr[4];
    c[6]  =  0.31539156525252005f * sr[5];
    c[7]  = -1.0925484305920792f  * sr[6];
    c[8]  =  0.5462742152960396f  * sr[7];
    c[9]  = -0.5900435899266435f  * sr[8];
    c[10] =  2.890611442640554f   * sr[9];
    c[11] = -0.4570457994644658f  * sr[10];
    c[12] =  0.3731763325901154f  * sr[11];
    c[13] = -0.4570457994644658f  * sr[12];
    c[14] =  1.445305721320277f   * sr[13];
    c[15] = -0.5900435899266435f  * sr[14];

    float v[28];
    v[0] = xyz[g*3+0]; v[1] = xyz[g*3+1]; v[2] = xyz[g*3+2]; v[3] = T;
    v[4] = kk*Pxx; v[5] = kk*Pyy; v[6] = kk*Pzz;
    v[7] = 2.f*kk*Pxy; v[8] = 2.f*kk*Pxz; v[9] = 2.f*kk*Pyz;
    v[10] = op; v[11] = c[0];
#pragma unroll
    for (int i = 0; i < 15; ++i) v[12+i] = c[1+i];
    v[27] = 0.f;

    float2* o = (float2*)&g_prm2[g * U2G];
#pragma unroll
    for (int i = 0; i < 28; ++i) o[i] = make_float2(v[i], v[i]);
}

// ---------------------------------------------------------------------------
// Main kernel: 2 sorted-adjacent points per lane (packed f32x2). Warp-coherent
// distance cull: ~97% of (warp, gaussian) pairs skip after an 8-flop test.
// SH evaluated in e-space (Horner in rinv) so no normalized dirs needed.
// ---------------------------------------------------------------------------
__global__ void __launch_bounds__(128) main_kernel() {
    int tid = threadIdx.x;
    int gid = blockIdx.x * 128 + tid;      // lane-pair id: points 2*gid, 2*gid+1
    int split = blockIdx.y;

    float4 pa = g_spts[2*gid], pb = g_spts[2*gid+1];
    u64 npx = f2pack(pa.x, pb.x);
    u64 npy = f2pack(pa.y, pb.y);
    u64 npz = f2pack(pa.z, pb.z);

    const u64 K3  = 0x4040000040400000ULL;  // { 3, 3}
    const u64 K5  = 0x40A0000040A00000ULL;  // { 5, 5}
    const u64 Kn2 = 0xC0000000C0000000ULL;  // {-2,-2}
    const u64 Kn3 = 0xC0400000C0400000ULL;  // {-3,-3}
    const u64 SGN = 0x8000000080000000ULL;

    __shared__ ulonglong2 sB[TILE * U2G];

    u64 wacc = 0, ssacc = 0;
    int gbase = split * GPS;

    for (int t = 0; t < GPS; t += TILE) {
        __syncthreads();
        const ulonglong2* src = &g_prm2[(gbase + t) * U2G];
        for (int i = tid; i < TILE * U2G; i += 128) sB[i] = src[i];
        __syncthreads();

#pragma unroll 2
        for (int j = 0; j < TILE; ++j) {
            const ulonglong2* G = &sB[j * U2G];
            ulonglong2 q0 = G[0], q1 = G[1];

            u64 ex = f2add(q0.x, npx);   // e = gauss - point
            u64 ey = f2add(q0.y, npy);
            u64 ez = f2add(q1.x, npz);
            u64 exx = f2mul(ex, ex), eyy = f2mul(ey, ey), ezz = f2mul(ez, ez);
            u64 n2 = f2add(f2add(exx, eyy), ezz);

            float nA, nB; f2unpack(n2, nA, nB);
            float Tv, Tv2; f2unpack(q1.y, Tv, Tv2);
            bool act = (nA < Tv) || (nB < Tv);
            if (__ballot_sync(0xFFFFFFFFu, act)) {
                ulonglong2 q2 = G[2], q3 = G[3], q4 = G[4];
                u64 pxy = f2mul(ex, ey), pxz = f2mul(ex, ez), pyz = f2mul(ey, ez);

                // exponent (pre-scaled by -0.5*log2e)
                u64 mm = f2mul(exx, q2.x);
                mm = f2fma(eyy, q2.y, mm);
                mm = f2fma(ezz, q3.x, mm);
                mm = f2fma(pxy, q3.y, mm);
                mm = f2fma(pxz, q4.x, mm);
                mm = f2fma(pyz, q4.y, mm);

                // aux polynomials in e (negations on alu pipe via xor)
                u64 n2n  = n2 ^ SGN;
                u64 eyyn = eyy ^ SGN;
                u64 t6  = f2fma(K3, ezz, n2n);    // 3ezz - n2
                u64 uq  = f2add(exx, eyyn);       // exx - eyy
                u64 t9  = f2fma(K3, exx, eyyn);   // 3exx - eyy
                u64 w5  = f2fma(K5, ezz, n2n);    // 5ezz - n2
                u64 t12 = f2fma(Kn2, n2, w5);     // 5ezz - 3n2
                u64 t15 = f2fma(Kn3, ezz, uq);    // exx - eyy - 3ezz

                ulonglong2 q5 = G[5], q6 = G[6], q7 = G[7];
                // S1 (degree-1 in e)
                u64 S1 = f2fma(ex, q7.x, f2fma(ez, q6.y, f2mul(ey, q6.x)));
                ulonglong2 q8 = G[8], q9 = G[9];
                // S2 (degree-2 in e)
                u64 S2 = f2fma(uq, q9.y,
                         f2fma(pxz, q9.x,
                         f2fma(t6, q8.y,
                         f2fma(pyz, q8.x, f2mul(pxy, q7.y)))));
                ulonglong2 q10 = G[10], q11 = G[11], q12 = G[12], q13 = G[13];
                // S3 (degree-3 in e), two chains for ILP
                u64 m9  = f2mul(ey, t9);
                u64 m11 = f2mul(ey, w5);
                u64 m13 = f2mul(ex, w5);
                u64 m15 = f2mul(ex, t15);
                u64 S3a = f2mul(m9, q10.x);
                S3a = f2fma(m11, q11.x, S3a);
                S3a = f2fma(m13, q12.x, S3a);
                S3a = f2fma(m15, q13.x, S3a);
                u64 m10 = f2mul(pxy, ez);
                u64 m12 = f2mul(ez, t12);
                u64 m14 = f2mul(ez, uq);
                u64 S3b = f2mul(m10, q10.y);
                S3b = f2fma(m12, q11.y, S3b);
                S3b = f2fma(m14, q12.y, S3b);
                u64 S3 = f2add(S3a, S3b);

                // Horner in rinv: res = c0 + r*(S1 + r*(S2 + r*S3))
                u64 rq = f2pack(rsqf(nA), rsqf(nB));
                u64 res = f2fma(rq, S3, S2);
                res = f2fma(rq, res, S1);
                res = f2fma(rq, res, q5.y);

                float mA, mB; f2unpack(mm, mA, mB);
                u64 epk = f2pack(ex2f(mA), ex2f(mB));
                u64 w2 = f2mul(q5.x, epk);        // op * exp2(mm)
                wacc = f2add(wacc, w2);
                ssacc = f2fma(w2, f2relu(res), ssacc);
            }
        }
    }

    float wA, wB, sA, sB2;
    f2unpack(wacc, wA, wB);
    f2unpack(ssacc, sA, sB2);
    ((float2*)&g_partial[(split*2 + 0) * N_PTS])[gid] = make_float2(wA, wB);
    ((float2*)&g_partial[(split*2 + 1) * N_PTS])[gid] = make_float2(sA, sB2);
}

// ---------------------------------------------------------------------------
// Deterministic fixed-order reduction over splits + un-permute to original
// point order. out[0:N_PTS]=opacity, out[N_PTS:2N]=signal.
// ---------------------------------------------------------------------------
__global__ void reduce_kernel(float* __restrict__ out) {
    int slot = blockIdx.x * blockDim.x + threadIdx.x;
    if (slot >= N_PTS) return;
    float a = 0.f, b = 0.f;
#pragma unroll
    for (int s = 0; s < NSPLIT; ++s) {
        a += g_partial[(s*2 + 0) * N_PTS + slot];
        b += g_partial[(s*2 + 1) * N_PTS + slot];
    }
    int o = g_perm[slot];
    out[o] = a;
    out[N_PTS + o] = b;
}

extern "C" void kernel_launch(void* const* d_in, const int* in_sizes, int n_in,
                              void* d_out, int out_size) {
    const float* pts      = (const float*)d_in[0];  // network_pts
    // d_in[1] network_view, d_in[2] network_tx: unused by the reference math
    const float* xyz      = (const float*)d_in[3];
    const float* sh_dc    = (const float*)d_in[4];
    const float* sh_rest  = (const float*)d_in[5];
    const float* scaling  = (const float*)d_in[6];
    const float* rotation = (const float*)d_in[7];
    const float* opacity  = (const float*)d_in[8];

    zero_kernel<<<NCELL/256, 256>>>();
    cell_count<<<N_PTS/256, 256>>>(pts);
    scan_kernel<<<1, 1024>>>();
    scatter_kernel<<<N_PTS/256, 256>>>(pts);
    prep_kernel<<<(N_GAUSS + 255)/256, 256>>>(xyz, sh_dc, sh_rest, scaling, rotation, opacity);
    main_kernel<<<dim3(N_PTS/2/128, NSPLIT), 128>>>();
    reduce_kernel<<<(N_PTS + 255)/256, 256>>>((float*)d_out);
}